// round 12
// baseline (speedup 1.0000x reference)
#include <cuda_runtime.h>
#include <math.h>

#define IMGSZ 224
#define HW (IMGSZ*IMGSZ)     // 50176
#define NK 100
#define NP 16
#define NB 8
#define NT 196               // 14x14 tiles of 16x16 px
#define NITER 10
#define GRID_SLIC 784        // one block = same tile index of images b0 and b0+4

#define FIXSCALE 68719476736.0f   // 2^36
typedef unsigned long long u64;
typedef unsigned int u32;

// ---------------- device scratch (static, no runtime alloc) ----------------
__device__ float g_A[NP*IMGSZ];                   // resize matrix [16,224]
__device__ float g_centers[NB][NK][5];            // SLIC centers
__device__ u64 g_sum[NITER][NB][NK][4];           // exact sums: 3 colors (2^36 fix) + packed(cnt,py,px)
__device__ int g_ticket[NITER][NB];               // per-(iter,image) completion tickets
__device__ volatile int g_flag[NITER][NB];        // centers-ready flags
__device__ float g_acc[NB][NK][NP][NP][3];        // output accumulator (2.4 MB)

__device__ __forceinline__ float slic_ratio() {
    return (float)(10.0 / sqrt(224.0 * 224.0 / 100.0));
}

// ---------------- init: A, centers, zero g_sum/g_acc/tickets/flags ----------
__global__ void k_init(const float* __restrict__ x) {
    int b = blockIdx.x;
    int part = blockIdx.y;           // 0..3
    int t = threadIdx.x;

    if (part == 0) {
        if (b == 0 && t < NP) {
            float sample = (t + 0.5f) * 14.0f - 0.5f;
            float total = 0.0f;
            for (int h = 0; h < IMGSZ; h++) {
                float d = fabsf(sample - (float)h) * (1.0f / 14.0f);
                float w = fmaxf(0.0f, 1.0f - d);
                g_A[t * IMGSZ + h] = w;
                total += w;
            }
            float inv = 1.0f / total;
            for (int h = 0; h < IMGSZ; h++) g_A[t * IMGSZ + h] *= inv;
        }
        if (t < NK) {
            const int cg[10] = {11, 33, 56, 78, 100, 123, 145, 168, 190, 212};
            int gy = t / 10, gx = t % 10;
            int h = cg[gy], w = cg[gx];
            const float* im = x + (size_t)b * 3 * HW;
            float ratio = slic_ratio();
            g_centers[b][t][0] = im[0 * HW + h * IMGSZ + w];
            g_centers[b][t][1] = im[1 * HW + h * IMGSZ + w];
            g_centers[b][t][2] = im[2 * HW + h * IMGSZ + w];
            g_centers[b][t][3] = (float)h * ratio;
            g_centers[b][t][4] = (float)w * ratio;
        }
        if (t < NITER) {                 // reset EVERY launch (graph replays)
            g_ticket[t][b] = 0;
            g_flag[t][b] = 0;
        }
    }
    // zero g_sum slice for image b (NITER*NK*4 = 4000 u64), split over 4 parts
    for (int j = part * 256 + t; j < NITER * NK * 4; j += 1024)
        g_sum[j / (NK * 4)][b][0][j % (NK * 4)] = 0ull;
    // zero g_acc slice for image b, split over 4 parts
    {
        float4* ga = reinterpret_cast<float4*>(&g_acc[b][0][0][0][0]);
        for (int j = part * 256 + t; j < NK * NP * NP * 3 / 4; j += 1024)
            ga[j] = make_float4(0.f, 0.f, 0.f, 0.f);
    }
}

// ---------------- persistent SLIC: 10 iterations, distributed sync ----------
// Block j owns tile j%196 of images j/196 and j/196+4. Per iteration, per
// image: wait for g_flag[it-1][b] (centers ready), prune candidates, assign,
// REDUX-aggregate exact sums into g_sum[it][b], ticket; the block finishing
// the 196th tile of image b computes the image's centers (exact int64 ->
// double divide, bit-identical to the multi-launch version) and releases
// g_flag[it][b]. All cross-iteration global reads use __ldcg (L1 is not
// coherent across SMs inside one launch); release order is guaranteed by
// __threadfence before the flag store, observed through L2.
__global__ void __launch_bounds__(256, 6) k_slic(const float* __restrict__ x) {
    __shared__ float scen[NK][5];
    __shared__ float scen2[NK];
    __shared__ unsigned char scand[NK];
    __shared__ unsigned int bal[8];
    __shared__ int sminbits;
    __shared__ int is_last;

    int bid = blockIdx.x;                 // 0..783
    int t = threadIdx.x;
    int lane = t & 31, warp = t >> 5;
    const float ratio = slic_ratio();
    int tile = bid % NT;
    int b0 = bid / NT;                    // 0..3
    int tr = tile / 14, tc = tile - tr * 14;

    // per-pixel constants for this tile
    int py = tr * 16 + (t >> 4), px = tc * 16 + (t & 15);
    int i = py * IMGSZ + px;
    float f3 = (float)py * ratio;
    float f4 = (float)px * ratio;
    float ylo = (float)(tr * 16) * ratio, yhi = (float)(tr * 16 + 15) * ratio;
    float xlo = (float)(tc * 16) * ratio, xhi = (float)(tc * 16 + 15) * ratio;

    for (int it = 0; it < NITER; it++) {
        for (int half = 0; half < 2; half++) {
            int b = b0 + half * 4;

            // ---- wait for this image's centers from the previous iteration ----
            if (it > 0) {
                if (t == 0) {
                    while (g_flag[it - 1][b] == 0) __nanosleep(64);
                }
                __syncthreads();
            }
            if (t == 0) sminbits = 0x7f7fffff;   // +FLT_MAX
            __syncthreads();

            // ---- candidate prologue ----
            float rmin = 1e30f, rmax = 1e30f;
            float c0 = 0.f, c1 = 0.f, c2 = 0.f, c3 = 0.f, c4 = 0.f;
            if (t < NK) {
                const float* cp = &g_centers[b][t][0];
                c0 = __ldcg(cp + 0);
                c1 = __ldcg(cp + 1);
                c2 = __ldcg(cp + 2);
                c3 = __ldcg(cp + 3);
                c4 = __ldcg(cp + 4);
                float dy0 = fmaxf(0.0f, fmaxf(ylo - c3, c3 - yhi));
                float dx0 = fmaxf(0.0f, fmaxf(xlo - c4, c4 - xhi));
                float dy1 = fmaxf(c3 - ylo, yhi - c3);
                float dx1 = fmaxf(c4 - xlo, xhi - c4);
                rmin = dy0 * dy0 + dx0 * dx0;
                rmax = dy1 * dy1 + dx1 * dx1;
            }
            u32 mn = __reduce_min_sync(0xffffffffu, __float_as_uint(rmax));
            if (lane == 0) atomicMin(&sminbits, (int)mn);
            __syncthreads();
            float thresh = __int_as_float(sminbits) + 3.001f;
            bool keep = (t < NK) && (rmin <= thresh);
            unsigned int m = __ballot_sync(0xffffffffu, keep);
            if (lane == 0) bal[warp] = m;
            __syncthreads();
            if (keep) {
                int slot = __popc(m & ((1u << lane) - 1u));
                for (int w2 = 0; w2 < warp; w2++) slot += __popc(bal[w2]);
                scand[slot] = (unsigned char)t;
                scen[slot][0] = c0; scen[slot][1] = c1; scen[slot][2] = c2;
                scen[slot][3] = c3; scen[slot][4] = c4;
                scen2[slot] = c0*c0 + c1*c1 + c2*c2 + c3*c3 + c4*c4;
            }
            __syncthreads();
            int nc = 0;
#pragma unroll
            for (int w2 = 0; w2 < 8; w2++) nc += __popc(bal[w2]);

            // ---- per-pixel assignment ----
            const float* im = x + (size_t)b * 3 * HW;
            float f0 = im[i];
            float f1 = im[HW + i];
            float f2 = im[2 * HW + i];
            float fsq = f0*f0 + f1*f1 + f2*f2 + f3*f3 + f4*f4;

            float best = 3.4e38f;
            int bs = 0;
            for (int s = 0; s < nc; s++) {
                float dot = f0 * scen[s][0];
                dot = fmaf(f1, scen[s][1], dot);
                dot = fmaf(f2, scen[s][2], dot);
                dot = fmaf(f3, scen[s][3], dot);
                dot = fmaf(f4, scen[s][4], dot);
                float d = fsq + scen2[s] - 2.0f * dot;
                if (d < best) { best = d; bs = s; }   // strict < => first-min
            }
            int kk = scand[bs];

            // ---- REDUX-based exact accumulation ----
            u64 q0 = (u64)__float2ll_rn(f0 * FIXSCALE);   // < 2^36
            u64 q1 = (u64)__float2ll_rn(f1 * FIXSCALE);
            u64 q2 = (u64)__float2ll_rn(f2 * FIXSCALE);
            u32 l0 = (u32)q0 & 0x3FFFFu, h0 = (u32)(q0 >> 18);   // warp sums < 2^23
            u32 l1 = (u32)q1 & 0x3FFFFu, h1 = (u32)(q1 >> 18);
            u32 l2 = (u32)q2 & 0x3FFFFu, h2 = (u32)(q2 >> 18);

            unsigned int rem = 0xffffffffu;
            while (rem) {
                int leader = __ffs((int)rem) - 1;
                int lk = __shfl_sync(0xffffffffu, kk, leader);
                bool mine = (kk == lk);
                unsigned int mm = __ballot_sync(0xffffffffu, mine);
                if (mine) {
                    u32 s0l = __reduce_add_sync(mm, l0);
                    u32 s0h = __reduce_add_sync(mm, h0);
                    u32 s1l = __reduce_add_sync(mm, l1);
                    u32 s1h = __reduce_add_sync(mm, h1);
                    u32 s2l = __reduce_add_sync(mm, l2);
                    u32 s2h = __reduce_add_sync(mm, h2);
                    u32 spy = __reduce_add_sync(mm, (u32)py);
                    u32 spx = __reduce_add_sync(mm, (u32)px);
                    if (lane == leader) {
                        u64* gs = &g_sum[it][b][lk][0];
                        atomicAdd(gs + 0, ((u64)s0h << 18) + (u64)s0l);
                        atomicAdd(gs + 1, ((u64)s1h << 18) + (u64)s1l);
                        atomicAdd(gs + 2, ((u64)s2h << 18) + (u64)s2l);
                        // packed: cnt [0:16) | sum_py [16:40) | sum_px [40:64)
                        atomicAdd(gs + 3, (u64)__popc(mm) | ((u64)spy << 16) | ((u64)spx << 40));
                    }
                }
                rem &= ~mm;
            }

            // ---- ticket: last tile of image b computes its centers ----
            __threadfence();
            __syncthreads();
            if (t == 0) {
                int old = atomicAdd(&g_ticket[it][b], 1);
                is_last = (old == NT - 1);
            }
            __syncthreads();
            if (is_last) {
                if (t < NK) {
                    const u64* gs = &g_sum[it][b][t][0];
                    u64 a0 = __ldcg(gs + 0), a1 = __ldcg(gs + 1);
                    u64 a2 = __ldcg(gs + 2), sp = __ldcg(gs + 3);
                    u64 cnt = sp & 0xFFFFull;
                    u64 spy = (sp >> 16) & 0xFFFFFFull;
                    u64 spx = sp >> 40;
                    if (cnt > 0ull) {
                        double invc = 1.0 / (double)cnt;
                        double inv36 = invc * (1.0 / 68719476736.0);
                        g_centers[b][t][0] = (float)((double)a0 * inv36);
                        g_centers[b][t][1] = (float)((double)a1 * inv36);
                        g_centers[b][t][2] = (float)((double)a2 * inv36);
                        g_centers[b][t][3] = (float)((double)spy * invc * (double)ratio);
                        g_centers[b][t][4] = (float)((double)spx * invc * (double)ratio);
                    }
                    // cnt == 0: keep old center (matches jnp.where)
                }
                __threadfence();
                __syncthreads();
                if (t == 0) g_flag[it][b] = 1;     // release
            }
            __syncthreads();   // protect shared reuse across halves/iters
        }
    }
}

// ---------------- fused final-assign + scatter -------------------------------
// Block = 2 image rows (448 thr, 14 warps; warp = one 32-px row segment so h
// is warp-uniform). Prologue: candidate pruning over the strip, inline argmin
// (same math as k_slic => labels identical). Then scatter: per distinct
// label, per q: 3-channel float butterfly of wtq*rgb, leader REDGs wtp*sum.
__global__ __launch_bounds__(448) void k_scatter(const float* __restrict__ x) {
    __shared__ float scen[NK][5];
    __shared__ float scen2[NK];
    __shared__ unsigned char scand[NK];
    __shared__ unsigned int bal[14];
    __shared__ int sminbits;

    int strip = blockIdx.x, b = blockIdx.y, t = threadIdx.x;
    int lane = t & 31, warp = t >> 5;
    const float ratio = slic_ratio();

    if (t == 0) sminbits = 0x7f7fffff;
    __syncthreads();

    float rmin = 1e30f, rmax = 1e30f;
    float c0 = 0.f, c1 = 0.f, c2 = 0.f, c3 = 0.f, c4 = 0.f;
    if (t < NK) {
        c0 = g_centers[b][t][0];
        c1 = g_centers[b][t][1];
        c2 = g_centers[b][t][2];
        c3 = g_centers[b][t][3];
        c4 = g_centers[b][t][4];
        float ylo = (float)(strip * 2) * ratio, yhi = (float)(strip * 2 + 1) * ratio;
        float xlo = 0.0f, xhi = 223.0f * ratio;
        float dy0 = fmaxf(0.0f, fmaxf(ylo - c3, c3 - yhi));
        float dx0 = fmaxf(0.0f, fmaxf(xlo - c4, c4 - xhi));
        float dy1 = fmaxf(c3 - ylo, yhi - c3);
        float dx1 = fmaxf(c4 - xlo, xhi - c4);
        rmin = dy0 * dy0 + dx0 * dx0;
        rmax = dy1 * dy1 + dx1 * dx1;
    }
    u32 mn = __reduce_min_sync(0xffffffffu, __float_as_uint(rmax));
    if (lane == 0) atomicMin(&sminbits, (int)mn);
    __syncthreads();
    float thresh = __int_as_float(sminbits) + 3.001f;
    bool keep = (t < NK) && (rmin <= thresh);
    unsigned int m = __ballot_sync(0xffffffffu, keep);
    if (lane == 0) bal[warp] = m;
    __syncthreads();
    if (keep) {
        int slot = __popc(m & ((1u << lane) - 1u));
        for (int w2 = 0; w2 < warp; w2++) slot += __popc(bal[w2]);
        scand[slot] = (unsigned char)t;
        scen[slot][0] = c0; scen[slot][1] = c1; scen[slot][2] = c2;
        scen[slot][3] = c3; scen[slot][4] = c4;
        scen2[slot] = c0*c0 + c1*c1 + c2*c2 + c3*c3 + c4*c4;
    }
    __syncthreads();
    int nc = 0;
#pragma unroll
    for (int w2 = 0; w2 < 14; w2++) nc += __popc(bal[w2]);

    // ---- pixel features + assignment ----
    int row = warp / 7, seg = warp - row * 7;
    int h = strip * 2 + row;
    int w = seg * 32 + lane;
    int i = h * IMGSZ + w;
    const float* im = x + (size_t)b * 3 * HW;
    float r = im[i], g = im[HW + i], bl = im[2 * HW + i];
    float f3 = (float)h * ratio;
    float f4 = (float)w * ratio;
    float fsq = r*r + g*g + bl*bl + f3*f3 + f4*f4;

    float best = 3.4e38f;
    int bs = 0;
    for (int s = 0; s < nc; s++) {
        float dot = r * scen[s][0];
        dot = fmaf(g,  scen[s][1], dot);
        dot = fmaf(bl, scen[s][2], dot);
        dot = fmaf(f3, scen[s][3], dot);
        dot = fmaf(f4, scen[s][4], dot);
        float d = fsq + scen2[s] - 2.0f * dot;
        if (d < best) { best = d; bs = s; }
    }
    int kk = scand[bs];

    // ---- scatter (h warp-uniform) ----
    int p0 = max(0, (int)ceilf((h - 20.5f) * (1.0f / 14.0f)));
    int p1 = min(NP - 1, (int)floorf((h + 7.5f) * (1.0f / 14.0f)));
    int w0 = seg * 32;
    int qlo = max(0, (int)ceilf((w0 - 20.5f) * (1.0f / 14.0f)));
    int qhi = min(NP - 1, (int)floorf((w0 + 31 + 7.5f) * (1.0f / 14.0f)));

    unsigned int rem = 0xffffffffu;
    while (rem) {
        int leader = __ffs((int)rem) - 1;
        int lk = __shfl_sync(0xffffffffu, kk, leader);
        bool mine = (kk == lk);
        unsigned int mm = __ballot_sync(0xffffffffu, mine);
        for (int q = qlo; q <= qhi; q++) {
            float wtq = g_A[q * IMGSZ + w];          // exactly 0 outside support
            float v0 = mine ? wtq * r  : 0.f;
            float v1 = mine ? wtq * g  : 0.f;
            float v2 = mine ? wtq * bl : 0.f;
#pragma unroll
            for (int o = 16; o; o >>= 1) {
                v0 += __shfl_xor_sync(0xffffffffu, v0, o);
                v1 += __shfl_xor_sync(0xffffffffu, v1, o);
                v2 += __shfl_xor_sync(0xffffffffu, v2, o);
            }
            if (lane == leader) {
                for (int p = p0; p <= p1; p++) {
                    float wtp = g_A[p * IMGSZ + h];
                    if (wtp != 0.0f) {
                        float* dst = &g_acc[b][lk][p][q][0];
                        atomicAdd(dst + 0, wtp * v0);
                        atomicAdd(dst + 1, wtp * v1);
                        atomicAdd(dst + 2, wtp * v2);
                    }
                }
            }
        }
        rem &= ~mm;
    }
}

// ---------------- output permutation ----------------
__global__ void k_out(float* __restrict__ out) {
    int b = blockIdx.y;
    int lin = blockIdx.x * 1024 + threadIdx.x;       // < 76800
    float v = (&g_acc[b][0][0][0][0])[lin];
    int kc = lin >> 8;           // / 256
    int s  = lin & 255;          // % 256
    out[((size_t)b * 256 + s) * 300 + kc] = v;
}

// ---------------- launch ----------------
extern "C" void kernel_launch(void* const* d_in, const int* in_sizes, int n_in,
                              void* d_out, int out_size) {
    const float* x = (const float*)d_in[0];
    float* out = (float*)d_out;

    k_init<<<dim3(NB, 4), 256>>>(x);
    k_slic<<<GRID_SLIC, 256>>>(x);          // all 10 iterations, one launch
    k_scatter<<<dim3(112, NB), 448>>>(x);   // final assign fused with scatter
    k_out<<<dim3(75, NB), 1024>>>(out);
}

// round 15
// speedup vs baseline: 1.2151x; 1.2151x over previous
#include <cuda_runtime.h>
#include <math.h>

#define IMGSZ 224
#define HW (IMGSZ*IMGSZ)     // 50176
#define NK 100
#define NP 16
#define NB 8
#define NTT 98               // 14x7 tiles of 16(rows)x32(cols) px
#define NITER 10

#define FIXSCALE 68719476736.0f   // 2^36
typedef unsigned long long u64;
typedef unsigned int u32;

// ---------------- device scratch (static, no runtime alloc) ----------------
__device__ float g_A[NP*IMGSZ];                   // resize matrix [16,224]
__device__ float g_centers[NB][NK][5];            // SLIC centers
__device__ u64 g_sum[NITER][NB][NK][4];           // exact sums: 3 colors (2^36 fix) + packed(cnt,py,px)
__device__ int g_ticket[NITER][NB];               // per-(iter,image) completion tickets

__device__ __forceinline__ float slic_ratio() {
    return (float)(10.0 / sqrt(224.0 * 224.0 / 100.0));
}

// ---------------- init: A, centers, zero g_sum/tickets/out ------------------
__global__ void k_init(const float* __restrict__ x, float* __restrict__ out) {
    int b = blockIdx.x;
    int part = blockIdx.y;           // 0..3
    int t = threadIdx.x;

    if (part == 0) {
        if (b == 0 && t < NP) {
            float sample = (t + 0.5f) * 14.0f - 0.5f;
            float total = 0.0f;
            for (int h = 0; h < IMGSZ; h++) {
                float d = fabsf(sample - (float)h) * (1.0f / 14.0f);
                float w = fmaxf(0.0f, 1.0f - d);
                g_A[t * IMGSZ + h] = w;
                total += w;
            }
            float inv = 1.0f / total;
            for (int h = 0; h < IMGSZ; h++) g_A[t * IMGSZ + h] *= inv;
        }
        if (t < NK) {
            const int cg[10] = {11, 33, 56, 78, 100, 123, 145, 168, 190, 212};
            int gy = t / 10, gx = t % 10;
            int h = cg[gy], w = cg[gx];
            const float* im = x + (size_t)b * 3 * HW;
            float ratio = slic_ratio();
            g_centers[b][t][0] = im[0 * HW + h * IMGSZ + w];
            g_centers[b][t][1] = im[1 * HW + h * IMGSZ + w];
            g_centers[b][t][2] = im[2 * HW + h * IMGSZ + w];
            g_centers[b][t][3] = (float)h * ratio;
            g_centers[b][t][4] = (float)w * ratio;
        }
        if (t < NITER) g_ticket[t][b] = 0;   // reset EVERY launch (graph replays)
    }
    // zero g_sum slice for image b (NITER*NK*4 = 4000 u64), split over 4 parts
    for (int j = part * 256 + t; j < NITER * NK * 4; j += 1024)
        g_sum[j / (NK * 4)][b][0][j % (NK * 4)] = 0ull;
    // zero the output slice for image b (76800 floats = 19200 float4)
    {
        float4* go = reinterpret_cast<float4*>(out + (size_t)b * 256 * 300);
        for (int j = part * 256 + t; j < 256 * 300 / 4; j += 1024)
            go[j] = make_float4(0.f, 0.f, 0.f, 0.f);
    }
}

// ---------------- fused assign (2 px/thread) + exact sums + ticket ----------
// One block per 16(rows)x32(cols) tile; thread t handles pixels
// (row=t>>4, col=t&15) and (row, col+16). Warp = 2 full rows.
// Candidate pruning: center k excluded iff rectMinSpatial2(k) >
// min_j rectMaxSpatial2(j) + 3 (colors in [0,1)). Conservative => labels
// identical to full argmin. Accumulation: colors quantized at 2^36, split
// 18/19 bits, warp-summed with __reduce_add_sync (exact); spatial sums as
// raw ints packed in one u64. LAST block per image recomputes centers.
__global__ __launch_bounds__(256) void k_assign_tile(const float* __restrict__ x,
                                                     int iter) {
    __shared__ float scen[NK][5];
    __shared__ float scen2[NK];
    __shared__ unsigned char scand[NK];
    __shared__ unsigned int bal[8];
    __shared__ int sminbits;
    __shared__ int is_last;

    int tile = blockIdx.x, b = blockIdx.y, t = threadIdx.x;
    int lane = t & 31, warp = t >> 5;
    const float ratio = slic_ratio();
    int tr = tile / 7, tc = tile - tr * 7;       // 14 x 7 tiles

    if (t == 0) sminbits = 0x7f7fffff;   // +FLT_MAX
    __syncthreads();

    // ---- candidate prologue ----
    float rmin = 1e30f, rmax = 1e30f;
    float c0 = 0.f, c1 = 0.f, c2 = 0.f, c3 = 0.f, c4 = 0.f;
    if (t < NK) {
        c0 = g_centers[b][t][0];
        c1 = g_centers[b][t][1];
        c2 = g_centers[b][t][2];
        c3 = g_centers[b][t][3];
        c4 = g_centers[b][t][4];
        float ylo = (float)(tr * 16) * ratio, yhi = (float)(tr * 16 + 15) * ratio;
        float xlo = (float)(tc * 32) * ratio, xhi = (float)(tc * 32 + 31) * ratio;
        float dy0 = fmaxf(0.0f, fmaxf(ylo - c3, c3 - yhi));
        float dx0 = fmaxf(0.0f, fmaxf(xlo - c4, c4 - xhi));
        float dy1 = fmaxf(c3 - ylo, yhi - c3);
        float dx1 = fmaxf(c4 - xlo, xhi - c4);
        rmin = dy0 * dy0 + dx0 * dx0;
        rmax = dy1 * dy1 + dx1 * dx1;
    }
    u32 mn = __reduce_min_sync(0xffffffffu, __float_as_uint(rmax));  // nonneg floats
    if (lane == 0) atomicMin(&sminbits, (int)mn);
    __syncthreads();
    float thresh = __int_as_float(sminbits) + 3.001f;
    bool keep = (t < NK) && (rmin <= thresh);
    unsigned int m = __ballot_sync(0xffffffffu, keep);
    if (lane == 0) bal[warp] = m;
    __syncthreads();
    if (keep) {
        int slot = __popc(m & ((1u << lane) - 1u));
        for (int w2 = 0; w2 < warp; w2++) slot += __popc(bal[w2]);
        scand[slot] = (unsigned char)t;
        scen[slot][0] = c0; scen[slot][1] = c1; scen[slot][2] = c2;
        scen[slot][3] = c3; scen[slot][4] = c4;
        scen2[slot] = c0*c0 + c1*c1 + c2*c2 + c3*c3 + c4*c4;
    }
    __syncthreads();
    int nc = 0;
#pragma unroll
    for (int w2 = 0; w2 < 8; w2++) nc += __popc(bal[w2]);

    // ---- two pixels per thread ----
    int py  = tr * 16 + (t >> 4);
    int pxa = tc * 32 + (t & 15);
    int pxb = pxa + 16;
    int ia = py * IMGSZ + pxa;
    const float* im = x + (size_t)b * 3 * HW;
    float a0 = im[ia],       b0 = im[ia + 16];
    float a1 = im[HW + ia],  b1 = im[HW + ia + 16];
    float a2 = im[2*HW + ia],b2 = im[2*HW + ia + 16];
    float f3  = (float)py * ratio;
    float f4a = (float)pxa * ratio;
    float f4b = (float)pxb * ratio;
    float fsqa = a0*a0 + a1*a1 + a2*a2 + f3*f3 + f4a*f4a;
    float fsqb = b0*b0 + b1*b1 + b2*b2 + f3*f3 + f4b*f4b;

    float bestA = 3.4e38f, bestB = 3.4e38f;
    int bsA = 0, bsB = 0;
    for (int s = 0; s < nc; s++) {
        float s0 = scen[s][0], s1 = scen[s][1], s2 = scen[s][2];
        float s3 = scen[s][3], s4 = scen[s][4], ss = scen2[s];
        float dA = a0 * s0;
        float dB = b0 * s0;
        dA = fmaf(a1, s1, dA);  dB = fmaf(b1, s1, dB);
        dA = fmaf(a2, s2, dA);  dB = fmaf(b2, s2, dB);
        dA = fmaf(f3, s3, dA);  dB = fmaf(f3, s3, dB);
        dA = fmaf(f4a, s4, dA); dB = fmaf(f4b, s4, dB);
        float eA = fsqa + ss - 2.0f * dA;
        float eB = fsqb + ss - 2.0f * dB;
        if (eA < bestA) { bestA = eA; bsA = s; }   // strict < => first-min
        if (eB < bestB) { bestB = eB; bsB = s; }
    }
    int kkA = scand[bsA];
    int kkB = scand[bsB];

    // ---- REDUX-based exact accumulation (two passes: pixel A then B) ----
#pragma unroll
    for (int pass = 0; pass < 2; pass++) {
        float v0 = pass ? b0 : a0;
        float v1 = pass ? b1 : a1;
        float v2 = pass ? b2 : a2;
        int   kk = pass ? kkB : kkA;
        int   px = pass ? pxb : pxa;
        u64 q0 = (u64)__float2ll_rn(v0 * FIXSCALE);   // < 2^36
        u64 q1 = (u64)__float2ll_rn(v1 * FIXSCALE);
        u64 q2 = (u64)__float2ll_rn(v2 * FIXSCALE);
        u32 l0 = (u32)q0 & 0x3FFFFu, h0 = (u32)(q0 >> 18);   // warp sums < 2^23
        u32 l1 = (u32)q1 & 0x3FFFFu, h1 = (u32)(q1 >> 18);
        u32 l2 = (u32)q2 & 0x3FFFFu, h2 = (u32)(q2 >> 18);

        unsigned int rem = 0xffffffffu;
        while (rem) {
            int leader = __ffs((int)rem) - 1;
            int lk = __shfl_sync(0xffffffffu, kk, leader);
            bool mine = (kk == lk);
            unsigned int mm = __ballot_sync(0xffffffffu, mine);
            if (mine) {
                u32 s0l = __reduce_add_sync(mm, l0);
                u32 s0h = __reduce_add_sync(mm, h0);
                u32 s1l = __reduce_add_sync(mm, l1);
                u32 s1h = __reduce_add_sync(mm, h1);
                u32 s2l = __reduce_add_sync(mm, l2);
                u32 s2h = __reduce_add_sync(mm, h2);
                u32 spy = __reduce_add_sync(mm, (u32)py);
                u32 spx = __reduce_add_sync(mm, (u32)px);
                if (lane == leader) {
                    u64* gs = &g_sum[iter][b][lk][0];
                    atomicAdd(gs + 0, ((u64)s0h << 18) + (u64)s0l);
                    atomicAdd(gs + 1, ((u64)s1h << 18) + (u64)s1l);
                    atomicAdd(gs + 2, ((u64)s2h << 18) + (u64)s2l);
                    // packed: cnt [0:16) | sum_py [16:40) | sum_px [40:64)
                    atomicAdd(gs + 3, (u64)__popc(mm) | ((u64)spy << 16) | ((u64)spx << 40));
                }
            }
            rem &= ~mm;
        }
    }

    // ---- last block per image computes next centers ----
    __threadfence();
    __syncthreads();
    if (t == 0) {
        int old = atomicAdd(&g_ticket[iter][b], 1);
        is_last = (old == NTT - 1);
    }
    __syncthreads();
    if (is_last && t < NK) {
        const u64* gs = &g_sum[iter][b][t][0];
        u64 s0 = gs[0], s1 = gs[1], s2 = gs[2], sp = gs[3];
        u64 cnt = sp & 0xFFFFull;
        u64 spy = (sp >> 16) & 0xFFFFFFull;
        u64 spx = sp >> 40;
        if (cnt > 0ull) {
            double invc = 1.0 / (double)cnt;
            double inv36 = invc * (1.0 / 68719476736.0);
            g_centers[b][t][0] = (float)((double)s0 * inv36);
            g_centers[b][t][1] = (float)((double)s1 * inv36);
            g_centers[b][t][2] = (float)((double)s2 * inv36);
            g_centers[b][t][3] = (float)((double)spy * invc * (double)ratio);
            g_centers[b][t][4] = (float)((double)spx * invc * (double)ratio);
        }
        // cnt == 0: keep old center (matches jnp.where)
    }
}

// ---------------- fused final-assign + scatter directly into out ------------
// Block = 2 image rows (448 thr, 14 warps; warp = one 32-px row segment so h
// is warp-uniform). Prologue: candidate pruning over the strip, inline argmin
// (same math as k_assign_tile => labels identical). Scatter: per distinct
// label, per q: 3-channel float butterfly of wtq*rgb, leader atomically adds
// wtp*sum straight into d_out at the permuted (s,kc) address.
__global__ __launch_bounds__(448) void k_scatter(const float* __restrict__ x,
                                                 float* __restrict__ out) {
    __shared__ float scen[NK][5];
    __shared__ float scen2[NK];
    __shared__ unsigned char scand[NK];
    __shared__ unsigned int bal[14];
    __shared__ int sminbits;

    int strip = blockIdx.x, b = blockIdx.y, t = threadIdx.x;
    int lane = t & 31, warp = t >> 5;
    const float ratio = slic_ratio();

    if (t == 0) sminbits = 0x7f7fffff;
    __syncthreads();

    float rmin = 1e30f, rmax = 1e30f;
    float c0 = 0.f, c1 = 0.f, c2 = 0.f, c3 = 0.f, c4 = 0.f;
    if (t < NK) {
        c0 = g_centers[b][t][0];
        c1 = g_centers[b][t][1];
        c2 = g_centers[b][t][2];
        c3 = g_centers[b][t][3];
        c4 = g_centers[b][t][4];
        float ylo = (float)(strip * 2) * ratio, yhi = (float)(strip * 2 + 1) * ratio;
        float xlo = 0.0f, xhi = 223.0f * ratio;
        float dy0 = fmaxf(0.0f, fmaxf(ylo - c3, c3 - yhi));
        float dx0 = fmaxf(0.0f, fmaxf(xlo - c4, c4 - xhi));
        float dy1 = fmaxf(c3 - ylo, yhi - c3);
        float dx1 = fmaxf(c4 - xlo, xhi - c4);
        rmin = dy0 * dy0 + dx0 * dx0;
        rmax = dy1 * dy1 + dx1 * dx1;
    }
    u32 mn = __reduce_min_sync(0xffffffffu, __float_as_uint(rmax));
    if (lane == 0) atomicMin(&sminbits, (int)mn);
    __syncthreads();
    float thresh = __int_as_float(sminbits) + 3.001f;
    bool keep = (t < NK) && (rmin <= thresh);
    unsigned int m = __ballot_sync(0xffffffffu, keep);
    if (lane == 0) bal[warp] = m;
    __syncthreads();
    if (keep) {
        int slot = __popc(m & ((1u << lane) - 1u));
        for (int w2 = 0; w2 < warp; w2++) slot += __popc(bal[w2]);
        scand[slot] = (unsigned char)t;
        scen[slot][0] = c0; scen[slot][1] = c1; scen[slot][2] = c2;
        scen[slot][3] = c3; scen[slot][4] = c4;
        scen2[slot] = c0*c0 + c1*c1 + c2*c2 + c3*c3 + c4*c4;
    }
    __syncthreads();
    int nc = 0;
#pragma unroll
    for (int w2 = 0; w2 < 14; w2++) nc += __popc(bal[w2]);

    // ---- pixel features + assignment ----
    int row = warp / 7, seg = warp - row * 7;
    int h = strip * 2 + row;
    int w = seg * 32 + lane;
    int i = h * IMGSZ + w;
    const float* im = x + (size_t)b * 3 * HW;
    float r = im[i], g = im[HW + i], bl = im[2 * HW + i];
    float f3 = (float)h * ratio;
    float f4 = (float)w * ratio;
    float fsq = r*r + g*g + bl*bl + f3*f3 + f4*f4;

    float best = 3.4e38f;
    int bs = 0;
    for (int s = 0; s < nc; s++) {
        float dot = r * scen[s][0];
        dot = fmaf(g,  scen[s][1], dot);
        dot = fmaf(bl, scen[s][2], dot);
        dot = fmaf(f3, scen[s][3], dot);
        dot = fmaf(f4, scen[s][4], dot);
        float d = fsq + scen2[s] - 2.0f * dot;
        if (d < best) { best = d; bs = s; }
    }
    int kk = scand[bs];

    // ---- scatter (h warp-uniform) directly into out ----
    int p0 = max(0, (int)ceilf((h - 20.5f) * (1.0f / 14.0f)));
    int p1 = min(NP - 1, (int)floorf((h + 7.5f) * (1.0f / 14.0f)));
    int w0 = seg * 32;
    int qlo = max(0, (int)ceilf((w0 - 20.5f) * (1.0f / 14.0f)));
    int qhi = min(NP - 1, (int)floorf((w0 + 31 + 7.5f) * (1.0f / 14.0f)));

    float* ob = out + (size_t)b * 256 * 300;

    unsigned int rem = 0xffffffffu;
    while (rem) {
        int leader = __ffs((int)rem) - 1;
        int lk = __shfl_sync(0xffffffffu, kk, leader);
        bool mine = (kk == lk);
        unsigned int mm = __ballot_sync(0xffffffffu, mine);
        for (int q = qlo; q <= qhi; q++) {
            float wtq = g_A[q * IMGSZ + w];          // exactly 0 outside support
            float v0 = mine ? wtq * r  : 0.f;
            float v1 = mine ? wtq * g  : 0.f;
            float v2 = mine ? wtq * bl : 0.f;
#pragma unroll
            for (int o = 16; o; o >>= 1) {
                v0 += __shfl_xor_sync(0xffffffffu, v0, o);
                v1 += __shfl_xor_sync(0xffffffffu, v1, o);
                v2 += __shfl_xor_sync(0xffffffffu, v2, o);
            }
            if (lane == leader) {
                for (int p = p0; p <= p1; p++) {
                    float wtp = g_A[p * IMGSZ + h];
                    if (wtp != 0.0f) {
                        int lin = ((lk * 16 + p) * 16 + q) * 3;   // channel c adds +c
#pragma unroll
                        for (int c = 0; c < 3; c++) {
                            int lc = lin + c;
                            int s_  = lc & 255;
                            int kc  = lc >> 8;
                            float vv = (c == 0) ? v0 : (c == 1) ? v1 : v2;
                            atomicAdd(ob + s_ * 300 + kc, wtp * vv);
                        }
                    }
                }
            }
        }
        rem &= ~mm;
    }
}

// ---------------- launch ----------------
extern "C" void kernel_launch(void* const* d_in, const int* in_sizes, int n_in,
                              void* d_out, int out_size) {
    const float* x = (const float*)d_in[0];
    float* out = (float*)d_out;

    k_init<<<dim3(NB, 4), 256>>>(x, out);

    dim3 gt(NTT, NB);                    // 98 x 8
    for (int it = 0; it < NITER; it++)
        k_assign_tile<<<gt, 256>>>(x, it);

    k_scatter<<<dim3(112, NB), 448>>>(x, out);   // final assign + scatter into out
}

// round 16
// speedup vs baseline: 1.2190x; 1.0032x over previous
#include <cuda_runtime.h>
#include <math.h>

#define IMGSZ 224
#define HW (IMGSZ*IMGSZ)     // 50176
#define NK 100
#define NP 16
#define NB 8
#define NTT 98               // 14x7 tiles of 16(rows)x32(cols) px
#define NITER 10

#define FIXSCALE 67108864.0f      // 2^26: warp color sums fit u32, image sums fit u64
typedef unsigned long long u64;
typedef unsigned int u32;

// ---------------- device scratch (static, no runtime alloc) ----------------
__device__ float g_A[NP*IMGSZ];                   // resize matrix [16,224]
__device__ float g_centers[NB][NK][5];            // SLIC centers
__device__ u64 g_sum[NITER][NB][NK][4];           // exact sums: 3 colors (2^26 fix) + packed(cnt,py,px)
__device__ int g_ticket[NITER][NB];               // per-(iter,image) completion tickets

__device__ __forceinline__ float slic_ratio() {
    return (float)(10.0 / sqrt(224.0 * 224.0 / 100.0));
}

// ---------------- init: A, centers, zero g_sum/tickets/out ------------------
__global__ void k_init(const float* __restrict__ x, float* __restrict__ out) {
    int b = blockIdx.x;
    int part = blockIdx.y;           // 0..3
    int t = threadIdx.x;

    if (part == 0) {
        if (b == 0 && t < NP) {
            float sample = (t + 0.5f) * 14.0f - 0.5f;
            float total = 0.0f;
            for (int h = 0; h < IMGSZ; h++) {
                float d = fabsf(sample - (float)h) * (1.0f / 14.0f);
                float w = fmaxf(0.0f, 1.0f - d);
                g_A[t * IMGSZ + h] = w;
                total += w;
            }
            float inv = 1.0f / total;
            for (int h = 0; h < IMGSZ; h++) g_A[t * IMGSZ + h] *= inv;
        }
        if (t < NK) {
            const int cg[10] = {11, 33, 56, 78, 100, 123, 145, 168, 190, 212};
            int gy = t / 10, gx = t % 10;
            int h = cg[gy], w = cg[gx];
            const float* im = x + (size_t)b * 3 * HW;
            float ratio = slic_ratio();
            g_centers[b][t][0] = im[0 * HW + h * IMGSZ + w];
            g_centers[b][t][1] = im[1 * HW + h * IMGSZ + w];
            g_centers[b][t][2] = im[2 * HW + h * IMGSZ + w];
            g_centers[b][t][3] = (float)h * ratio;
            g_centers[b][t][4] = (float)w * ratio;
        }
        if (t < NITER) g_ticket[t][b] = 0;   // reset EVERY launch (graph replays)
    }
    // zero g_sum slice for image b (NITER*NK*4 = 4000 u64), split over 4 parts
    for (int j = part * 256 + t; j < NITER * NK * 4; j += 1024)
        g_sum[j / (NK * 4)][b][0][j % (NK * 4)] = 0ull;
    // zero the output slice for image b (76800 floats = 19200 float4)
    {
        float4* go = reinterpret_cast<float4*>(out + (size_t)b * 256 * 300);
        for (int j = part * 256 + t; j < 256 * 300 / 4; j += 1024)
            go[j] = make_float4(0.f, 0.f, 0.f, 0.f);
    }
}

// ---------------- fused assign (2 px/thread) + exact sums + ticket ----------
// One block per 16(rows)x32(cols) tile; thread t handles pixels
// (row=t>>4, col=t&15) and (row, col+16). Warp = 2 full rows.
// Candidate pruning: center k excluded iff rectMinSpatial2(k) >
// min_j rectMaxSpatial2(j) + 3 (colors in [0,1)). Conservative => labels
// identical to full argmin. Accumulation: colors quantized at 2^26 => ONE
// u32 REDUX per color (warp sums < 2^31, exact, order-independent);
// spatial (py<<16)|px in one REDUX. 4 u64 atomics per (warp,label).
// LAST block per image recomputes centers from the exact sums.
__global__ __launch_bounds__(256) void k_assign_tile(const float* __restrict__ x,
                                                     int iter) {
    __shared__ float4 scen4[NK];     // c0..c3
    __shared__ float2 saux[NK];      // c4, sum(c^2)
    __shared__ unsigned char scand[NK];
    __shared__ unsigned int bal[8];
    __shared__ int sminbits;
    __shared__ int is_last;

    int tile = blockIdx.x, b = blockIdx.y, t = threadIdx.x;
    int lane = t & 31, warp = t >> 5;
    const float ratio = slic_ratio();
    int tr = tile / 7, tc = tile - tr * 7;       // 14 x 7 tiles

    if (t == 0) sminbits = 0x7f7fffff;   // +FLT_MAX
    __syncthreads();

    // ---- candidate prologue ----
    float rmin = 1e30f, rmax = 1e30f;
    float c0 = 0.f, c1 = 0.f, c2 = 0.f, c3 = 0.f, c4 = 0.f;
    if (t < NK) {
        c0 = g_centers[b][t][0];
        c1 = g_centers[b][t][1];
        c2 = g_centers[b][t][2];
        c3 = g_centers[b][t][3];
        c4 = g_centers[b][t][4];
        float ylo = (float)(tr * 16) * ratio, yhi = (float)(tr * 16 + 15) * ratio;
        float xlo = (float)(tc * 32) * ratio, xhi = (float)(tc * 32 + 31) * ratio;
        float dy0 = fmaxf(0.0f, fmaxf(ylo - c3, c3 - yhi));
        float dx0 = fmaxf(0.0f, fmaxf(xlo - c4, c4 - xhi));
        float dy1 = fmaxf(c3 - ylo, yhi - c3);
        float dx1 = fmaxf(c4 - xlo, xhi - c4);
        rmin = dy0 * dy0 + dx0 * dx0;
        rmax = dy1 * dy1 + dx1 * dx1;
    }
    u32 mn = __reduce_min_sync(0xffffffffu, __float_as_uint(rmax));  // nonneg floats
    if (lane == 0) atomicMin(&sminbits, (int)mn);
    __syncthreads();
    float thresh = __int_as_float(sminbits) + 3.001f;
    bool keep = (t < NK) && (rmin <= thresh);
    unsigned int m = __ballot_sync(0xffffffffu, keep);
    if (lane == 0) bal[warp] = m;
    __syncthreads();
    if (keep) {
        int slot = __popc(m & ((1u << lane) - 1u));
        for (int w2 = 0; w2 < warp; w2++) slot += __popc(bal[w2]);
        scand[slot] = (unsigned char)t;
        scen4[slot] = make_float4(c0, c1, c2, c3);
        saux[slot]  = make_float2(c4, c0*c0 + c1*c1 + c2*c2 + c3*c3 + c4*c4);
    }
    __syncthreads();
    int nc = 0;
#pragma unroll
    for (int w2 = 0; w2 < 8; w2++) nc += __popc(bal[w2]);

    // ---- two pixels per thread ----
    int py  = tr * 16 + (t >> 4);
    int pxa = tc * 32 + (t & 15);
    int pxb = pxa + 16;
    int ia = py * IMGSZ + pxa;
    const float* im = x + (size_t)b * 3 * HW;
    float a0 = im[ia],       b0 = im[ia + 16];
    float a1 = im[HW + ia],  b1 = im[HW + ia + 16];
    float a2 = im[2*HW + ia],b2 = im[2*HW + ia + 16];
    float f3  = (float)py * ratio;
    float f4a = (float)pxa * ratio;
    float f4b = (float)pxb * ratio;
    float fsqa = a0*a0 + a1*a1 + a2*a2 + f3*f3 + f4a*f4a;
    float fsqb = b0*b0 + b1*b1 + b2*b2 + f3*f3 + f4b*f4b;

    float bestA = 3.4e38f, bestB = 3.4e38f;
    int bsA = 0, bsB = 0;
    for (int s = 0; s < nc; s++) {
        float4 cc = scen4[s];
        float2 au = saux[s];
        float dA = a0 * cc.x;
        float dB = b0 * cc.x;
        dA = fmaf(a1,  cc.y, dA);  dB = fmaf(b1,  cc.y, dB);
        dA = fmaf(a2,  cc.z, dA);  dB = fmaf(b2,  cc.z, dB);
        dA = fmaf(f3,  cc.w, dA);  dB = fmaf(f3,  cc.w, dB);
        dA = fmaf(f4a, au.x, dA);  dB = fmaf(f4b, au.x, dB);
        float eA = fsqa + au.y - 2.0f * dA;
        float eB = fsqb + au.y - 2.0f * dB;
        if (eA < bestA) { bestA = eA; bsA = s; }   // strict < => first-min
        if (eB < bestB) { bestB = eB; bsB = s; }
    }
    int kkA = scand[bsA];
    int kkB = scand[bsB];

    // ---- REDUX-based exact accumulation (two passes: pixel A then B) ----
#pragma unroll
    for (int pass = 0; pass < 2; pass++) {
        float v0 = pass ? b0 : a0;
        float v1 = pass ? b1 : a1;
        float v2 = pass ? b2 : a2;
        int   kk = pass ? kkB : kkA;
        int   px = pass ? pxb : pxa;
        u32 qr = (u32)__float2int_rn(v0 * FIXSCALE);   // <= 2^26
        u32 qg = (u32)__float2int_rn(v1 * FIXSCALE);
        u32 qb = (u32)__float2int_rn(v2 * FIXSCALE);
        u32 qs = ((u32)py << 16) | (u32)px;            // spy,spx sums < 2^13: no carry

        unsigned int rem = 0xffffffffu;
        while (rem) {
            int leader = __ffs((int)rem) - 1;
            int lk = __shfl_sync(0xffffffffu, kk, leader);
            bool mine = (kk == lk);
            unsigned int mm = __ballot_sync(0xffffffffu, mine);
            if (mine) {
                u32 sr = __reduce_add_sync(mm, qr);    // < 2^31: exact
                u32 sg = __reduce_add_sync(mm, qg);
                u32 sb = __reduce_add_sync(mm, qb);
                u32 sp = __reduce_add_sync(mm, qs);
                if (lane == leader) {
                    u64* gs = &g_sum[iter][b][lk][0];
                    atomicAdd(gs + 0, (u64)sr);
                    atomicAdd(gs + 1, (u64)sg);
                    atomicAdd(gs + 2, (u64)sb);
                    // packed: cnt [0:16) | sum_py [16:40) | sum_px [40:64)
                    atomicAdd(gs + 3, (u64)__popc(mm) | ((u64)(sp >> 16) << 16)
                                      | ((u64)(sp & 0xFFFFu) << 40));
                }
            }
            rem &= ~mm;
        }
    }

    // ---- last block per image computes next centers ----
    __threadfence();
    __syncthreads();
    if (t == 0) {
        int old = atomicAdd(&g_ticket[iter][b], 1);
        is_last = (old == NTT - 1);
    }
    __syncthreads();
    if (is_last && t < NK) {
        const u64* gs = &g_sum[iter][b][t][0];
        u64 s0 = gs[0], s1 = gs[1], s2 = gs[2], sp = gs[3];
        u64 cnt = sp & 0xFFFFull;
        u64 spy = (sp >> 16) & 0xFFFFFFull;
        u64 spx = sp >> 40;
        if (cnt > 0ull) {
            double invc = 1.0 / (double)cnt;
            double inv26 = invc * (1.0 / 67108864.0);
            g_centers[b][t][0] = (float)((double)s0 * inv26);
            g_centers[b][t][1] = (float)((double)s1 * inv26);
            g_centers[b][t][2] = (float)((double)s2 * inv26);
            g_centers[b][t][3] = (float)((double)spy * invc * (double)ratio);
            g_centers[b][t][4] = (float)((double)spx * invc * (double)ratio);
        }
        // cnt == 0: keep old center (matches jnp.where)
    }
}

// ---------------- fused final-assign + scatter directly into out ------------
// Block = 2 image rows (448 thr, 14 warps; warp = one 32-px row segment so h
// is warp-uniform). Prologue: candidate pruning over the strip, inline argmin
// (same math as k_assign_tile => labels identical). Scatter: per distinct
// label, per q: 3-channel float butterfly of wtq*rgb, leader atomically adds
// wtp*sum straight into d_out at the permuted (s,kc) address.
__global__ __launch_bounds__(448) void k_scatter(const float* __restrict__ x,
                                                 float* __restrict__ out) {
    __shared__ float4 scen4[NK];
    __shared__ float2 saux[NK];
    __shared__ unsigned char scand[NK];
    __shared__ unsigned int bal[14];
    __shared__ int sminbits;

    int strip = blockIdx.x, b = blockIdx.y, t = threadIdx.x;
    int lane = t & 31, warp = t >> 5;
    const float ratio = slic_ratio();

    if (t == 0) sminbits = 0x7f7fffff;
    __syncthreads();

    float rmin = 1e30f, rmax = 1e30f;
    float c0 = 0.f, c1 = 0.f, c2 = 0.f, c3 = 0.f, c4 = 0.f;
    if (t < NK) {
        c0 = g_centers[b][t][0];
        c1 = g_centers[b][t][1];
        c2 = g_centers[b][t][2];
        c3 = g_centers[b][t][3];
        c4 = g_centers[b][t][4];
        float ylo = (float)(strip * 2) * ratio, yhi = (float)(strip * 2 + 1) * ratio;
        float xlo = 0.0f, xhi = 223.0f * ratio;
        float dy0 = fmaxf(0.0f, fmaxf(ylo - c3, c3 - yhi));
        float dx0 = fmaxf(0.0f, fmaxf(xlo - c4, c4 - xhi));
        float dy1 = fmaxf(c3 - ylo, yhi - c3);
        float dx1 = fmaxf(c4 - xlo, xhi - c4);
        rmin = dy0 * dy0 + dx0 * dx0;
        rmax = dy1 * dy1 + dx1 * dx1;
    }
    u32 mn = __reduce_min_sync(0xffffffffu, __float_as_uint(rmax));
    if (lane == 0) atomicMin(&sminbits, (int)mn);
    __syncthreads();
    float thresh = __int_as_float(sminbits) + 3.001f;
    bool keep = (t < NK) && (rmin <= thresh);
    unsigned int m = __ballot_sync(0xffffffffu, keep);
    if (lane == 0) bal[warp] = m;
    __syncthreads();
    if (keep) {
        int slot = __popc(m & ((1u << lane) - 1u));
        for (int w2 = 0; w2 < warp; w2++) slot += __popc(bal[w2]);
        scand[slot] = (unsigned char)t;
        scen4[slot] = make_float4(c0, c1, c2, c3);
        saux[slot]  = make_float2(c4, c0*c0 + c1*c1 + c2*c2 + c3*c3 + c4*c4);
    }
    __syncthreads();
    int nc = 0;
#pragma unroll
    for (int w2 = 0; w2 < 14; w2++) nc += __popc(bal[w2]);

    // ---- pixel features + assignment ----
    int row = warp / 7, seg = warp - row * 7;
    int h = strip * 2 + row;
    int w = seg * 32 + lane;
    int i = h * IMGSZ + w;
    const float* im = x + (size_t)b * 3 * HW;
    float r = im[i], g = im[HW + i], bl = im[2 * HW + i];
    float f3 = (float)h * ratio;
    float f4 = (float)w * ratio;
    float fsq = r*r + g*g + bl*bl + f3*f3 + f4*f4;

    float best = 3.4e38f;
    int bs = 0;
    for (int s = 0; s < nc; s++) {
        float4 cc = scen4[s];
        float2 au = saux[s];
        float dot = r * cc.x;
        dot = fmaf(g,  cc.y, dot);
        dot = fmaf(bl, cc.z, dot);
        dot = fmaf(f3, cc.w, dot);
        dot = fmaf(f4, au.x, dot);
        float d = fsq + au.y - 2.0f * dot;
        if (d < best) { best = d; bs = s; }
    }
    int kk = scand[bs];

    // ---- scatter (h warp-uniform) directly into out ----
    int p0 = max(0, (int)ceilf((h - 20.5f) * (1.0f / 14.0f)));
    int p1 = min(NP - 1, (int)floorf((h + 7.5f) * (1.0f / 14.0f)));
    int w0 = seg * 32;
    int qlo = max(0, (int)ceilf((w0 - 20.5f) * (1.0f / 14.0f)));
    int qhi = min(NP - 1, (int)floorf((w0 + 31 + 7.5f) * (1.0f / 14.0f)));

    float* ob = out + (size_t)b * 256 * 300;

    unsigned int rem = 0xffffffffu;
    while (rem) {
        int leader = __ffs((int)rem) - 1;
        int lk = __shfl_sync(0xffffffffu, kk, leader);
        bool mine = (kk == lk);
        unsigned int mm = __ballot_sync(0xffffffffu, mine);
        for (int q = qlo; q <= qhi; q++) {
            float wtq = g_A[q * IMGSZ + w];          // exactly 0 outside support
            float v0 = mine ? wtq * r  : 0.f;
            float v1 = mine ? wtq * g  : 0.f;
            float v2 = mine ? wtq * bl : 0.f;
#pragma unroll
            for (int o = 16; o; o >>= 1) {
                v0 += __shfl_xor_sync(0xffffffffu, v0, o);
                v1 += __shfl_xor_sync(0xffffffffu, v1, o);
                v2 += __shfl_xor_sync(0xffffffffu, v2, o);
            }
            if (lane == leader) {
                for (int p = p0; p <= p1; p++) {
                    float wtp = g_A[p * IMGSZ + h];
                    if (wtp != 0.0f) {
                        int lin = ((lk * 16 + p) * 16 + q) * 3;   // channel c adds +c
#pragma unroll
                        for (int c = 0; c < 3; c++) {
                            int lc = lin + c;
                            int s_  = lc & 255;
                            int kc  = lc >> 8;
                            float vv = (c == 0) ? v0 : (c == 1) ? v1 : v2;
                            atomicAdd(ob + s_ * 300 + kc, wtp * vv);
                        }
                    }
                }
            }
        }
        rem &= ~mm;
    }
}

// ---------------- launch ----------------
extern "C" void kernel_launch(void* const* d_in, const int* in_sizes, int n_in,
                              void* d_out, int out_size) {
    const float* x = (const float*)d_in[0];
    float* out = (float*)d_out;

    k_init<<<dim3(NB, 4), 256>>>(x, out);

    dim3 gt(NTT, NB);                    // 98 x 8
    for (int it = 0; it < NITER; it++)
        k_assign_tile<<<gt, 256>>>(x, it);

    k_scatter<<<dim3(112, NB), 448>>>(x, out);   // final assign + scatter into out
}

// round 17
// speedup vs baseline: 1.3035x; 1.0693x over previous
#include <cuda_runtime.h>
#include <math.h>

#define IMGSZ 224
#define HW (IMGSZ*IMGSZ)     // 50176
#define NK 100
#define NP 16
#define NB 8
#define NTT 98               // 14x7 tiles of 16(rows)x32(cols) px
#define NITER 10

#define FIXSCALE 67108864.0f      // 2^26
#define INVFIX   (1.0f / 67108864.0f)
typedef unsigned long long u64;
typedef unsigned int u32;

// ---------------- device scratch (static, no runtime alloc) ----------------
__device__ float g_A[NP*IMGSZ];                   // resize matrix [16,224]
__device__ float g_centers[NB][NK][5];            // SLIC centers
__device__ u64 g_sum[NITER][NB][NK][4];           // exact sums: 3 colors (2^26 fix) + packed(cnt,py,px)
__device__ int g_ticket[NITER][NB];               // per-(iter,image) completion tickets

__device__ __forceinline__ float slic_ratio() {
    return (float)(10.0 / sqrt(224.0 * 224.0 / 100.0));
}

// ---------------- init: A, centers, zero g_sum/tickets/out ------------------
__global__ void k_init(const float* __restrict__ x, float* __restrict__ out) {
    int b = blockIdx.x;
    int part = blockIdx.y;           // 0..3
    int t = threadIdx.x;

    if (part == 0) {
        if (b == 0 && t < NP) {
            float sample = (t + 0.5f) * 14.0f - 0.5f;
            float total = 0.0f;
            for (int h = 0; h < IMGSZ; h++) {
                float d = fabsf(sample - (float)h) * (1.0f / 14.0f);
                float w = fmaxf(0.0f, 1.0f - d);
                g_A[t * IMGSZ + h] = w;
                total += w;
            }
            float inv = 1.0f / total;
            for (int h = 0; h < IMGSZ; h++) g_A[t * IMGSZ + h] *= inv;
        }
        if (t < NK) {
            const int cg[10] = {11, 33, 56, 78, 100, 123, 145, 168, 190, 212};
            int gy = t / 10, gx = t % 10;
            int h = cg[gy], w = cg[gx];
            const float* im = x + (size_t)b * 3 * HW;
            float ratio = slic_ratio();
            g_centers[b][t][0] = im[0 * HW + h * IMGSZ + w];
            g_centers[b][t][1] = im[1 * HW + h * IMGSZ + w];
            g_centers[b][t][2] = im[2 * HW + h * IMGSZ + w];
            g_centers[b][t][3] = (float)h * ratio;
            g_centers[b][t][4] = (float)w * ratio;
        }
        if (t < NITER) g_ticket[t][b] = 0;   // reset EVERY launch (graph replays)
    }
    // zero g_sum slice for image b (NITER*NK*4 = 4000 u64), split over 4 parts
    for (int j = part * 256 + t; j < NITER * NK * 4; j += 1024)
        g_sum[j / (NK * 4)][b][0][j % (NK * 4)] = 0ull;
    // zero the output slice for image b (76800 floats = 19200 float4)
    {
        float4* go = reinterpret_cast<float4*>(out + (size_t)b * 256 * 300);
        for (int j = part * 256 + t; j < 256 * 300 / 4; j += 1024)
            go[j] = make_float4(0.f, 0.f, 0.f, 0.f);
    }
}

// ---------------- fused assign (2 px/thread) + exact sums + ticket ----------
// One block per 16(rows)x32(cols) tile; thread t handles pixels
// (row=t>>4, col=t&15) and (row, col+16). Warp = 2 full rows.
// Candidate pruning: center k excluded iff rectMinSpatial2(k) >
// min_j rectMaxSpatial2(j) + 3 (colors in [0,1)). Conservative => labels
// identical to full argmin. Accumulation: __match_any_sync partitions the
// warp by label in ONE instruction; all label-groups run their REDUX
// reductions concurrently (labeled-partition reduce). Colors quantized at
// 2^26 (exact, order-independent); spatial (py<<16)|px in one REDUX.
// 4 u64 atomics per (warp,label). LAST block per image recomputes centers.
__global__ __launch_bounds__(256) void k_assign_tile(const float* __restrict__ x,
                                                     int iter) {
    __shared__ float4 scen4[NK];     // c0..c3
    __shared__ float2 saux[NK];      // c4, sum(c^2)
    __shared__ unsigned char scand[NK];
    __shared__ unsigned int bal[8];
    __shared__ int sminbits;
    __shared__ int is_last;

    int tile = blockIdx.x, b = blockIdx.y, t = threadIdx.x;
    int lane = t & 31, warp = t >> 5;
    const float ratio = slic_ratio();
    int tr = tile / 7, tc = tile - tr * 7;       // 14 x 7 tiles

    if (t == 0) sminbits = 0x7f7fffff;   // +FLT_MAX
    __syncthreads();

    // ---- candidate prologue ----
    float rmin = 1e30f, rmax = 1e30f;
    float c0 = 0.f, c1 = 0.f, c2 = 0.f, c3 = 0.f, c4 = 0.f;
    if (t < NK) {
        c0 = g_centers[b][t][0];
        c1 = g_centers[b][t][1];
        c2 = g_centers[b][t][2];
        c3 = g_centers[b][t][3];
        c4 = g_centers[b][t][4];
        float ylo = (float)(tr * 16) * ratio, yhi = (float)(tr * 16 + 15) * ratio;
        float xlo = (float)(tc * 32) * ratio, xhi = (float)(tc * 32 + 31) * ratio;
        float dy0 = fmaxf(0.0f, fmaxf(ylo - c3, c3 - yhi));
        float dx0 = fmaxf(0.0f, fmaxf(xlo - c4, c4 - xhi));
        float dy1 = fmaxf(c3 - ylo, yhi - c3);
        float dx1 = fmaxf(c4 - xlo, xhi - c4);
        rmin = dy0 * dy0 + dx0 * dx0;
        rmax = dy1 * dy1 + dx1 * dx1;
    }
    u32 mn = __reduce_min_sync(0xffffffffu, __float_as_uint(rmax));  // nonneg floats
    if (lane == 0) atomicMin(&sminbits, (int)mn);
    __syncthreads();
    float thresh = __int_as_float(sminbits) + 3.001f;
    bool keep = (t < NK) && (rmin <= thresh);
    unsigned int m = __ballot_sync(0xffffffffu, keep);
    if (lane == 0) bal[warp] = m;
    __syncthreads();
    if (keep) {
        int slot = __popc(m & ((1u << lane) - 1u));
        for (int w2 = 0; w2 < warp; w2++) slot += __popc(bal[w2]);
        scand[slot] = (unsigned char)t;
        scen4[slot] = make_float4(c0, c1, c2, c3);
        saux[slot]  = make_float2(c4, c0*c0 + c1*c1 + c2*c2 + c3*c3 + c4*c4);
    }
    __syncthreads();
    int nc = 0;
#pragma unroll
    for (int w2 = 0; w2 < 8; w2++) nc += __popc(bal[w2]);

    // ---- two pixels per thread ----
    int py  = tr * 16 + (t >> 4);
    int pxa = tc * 32 + (t & 15);
    int pxb = pxa + 16;
    int ia = py * IMGSZ + pxa;
    const float* im = x + (size_t)b * 3 * HW;
    float a0 = im[ia],       b0 = im[ia + 16];
    float a1 = im[HW + ia],  b1 = im[HW + ia + 16];
    float a2 = im[2*HW + ia],b2 = im[2*HW + ia + 16];
    float f3  = (float)py * ratio;
    float f4a = (float)pxa * ratio;
    float f4b = (float)pxb * ratio;
    float fsqa = a0*a0 + a1*a1 + a2*a2 + f3*f3 + f4a*f4a;
    float fsqb = b0*b0 + b1*b1 + b2*b2 + f3*f3 + f4b*f4b;

    float bestA = 3.4e38f, bestB = 3.4e38f;
    int bsA = 0, bsB = 0;
    for (int s = 0; s < nc; s++) {
        float4 cc = scen4[s];
        float2 au = saux[s];
        float dA = a0 * cc.x;
        float dB = b0 * cc.x;
        dA = fmaf(a1,  cc.y, dA);  dB = fmaf(b1,  cc.y, dB);
        dA = fmaf(a2,  cc.z, dA);  dB = fmaf(b2,  cc.z, dB);
        dA = fmaf(f3,  cc.w, dA);  dB = fmaf(f3,  cc.w, dB);
        dA = fmaf(f4a, au.x, dA);  dB = fmaf(f4b, au.x, dB);
        float eA = fsqa + au.y - 2.0f * dA;
        float eB = fsqb + au.y - 2.0f * dB;
        if (eA < bestA) { bestA = eA; bsA = s; }   // strict < => first-min
        if (eB < bestB) { bestB = eB; bsB = s; }
    }
    int kkA = scand[bsA];
    int kkB = scand[bsB];

    // ---- match_any + REDUX exact accumulation (two passes: A then B) ----
#pragma unroll
    for (int pass = 0; pass < 2; pass++) {
        float v0 = pass ? b0 : a0;
        float v1 = pass ? b1 : a1;
        float v2 = pass ? b2 : a2;
        int   kk = pass ? kkB : kkA;
        int   px = pass ? pxb : pxa;
        u32 qr = (u32)__float2int_rn(v0 * FIXSCALE);   // <= 2^26
        u32 qg = (u32)__float2int_rn(v1 * FIXSCALE);
        u32 qb = (u32)__float2int_rn(v2 * FIXSCALE);
        u32 qs = ((u32)py << 16) | (u32)px;            // spy,spx sums < 2^13 per warp

        u32 mask = __match_any_sync(0xffffffffu, kk);  // label-partition, 1 instr
        u32 sr = __reduce_add_sync(mask, qr);          // all groups reduce concurrently
        u32 sg = __reduce_add_sync(mask, qg);
        u32 sb = __reduce_add_sync(mask, qb);
        u32 sp = __reduce_add_sync(mask, qs);
        if (lane == __ffs(mask) - 1) {
            u64* gs = &g_sum[iter][b][kk][0];
            atomicAdd(gs + 0, (u64)sr);
            atomicAdd(gs + 1, (u64)sg);
            atomicAdd(gs + 2, (u64)sb);
            // packed: cnt [0:16) | sum_py [16:40) | sum_px [40:64)
            atomicAdd(gs + 3, (u64)__popc(mask) | ((u64)(sp >> 16) << 16)
                              | ((u64)(sp & 0xFFFFu) << 40));
        }
    }

    // ---- last block per image computes next centers ----
    __threadfence();
    __syncthreads();
    if (t == 0) {
        int old = atomicAdd(&g_ticket[iter][b], 1);
        is_last = (old == NTT - 1);
    }
    __syncthreads();
    if (is_last && t < NK) {
        const u64* gs = &g_sum[iter][b][t][0];
        u64 s0 = gs[0], s1 = gs[1], s2 = gs[2], sp = gs[3];
        u64 cnt = sp & 0xFFFFull;
        u64 spy = (sp >> 16) & 0xFFFFFFull;
        u64 spx = sp >> 40;
        if (cnt > 0ull) {
            double invc = 1.0 / (double)cnt;
            double inv26 = invc * (1.0 / 67108864.0);
            g_centers[b][t][0] = (float)((double)s0 * inv26);
            g_centers[b][t][1] = (float)((double)s1 * inv26);
            g_centers[b][t][2] = (float)((double)s2 * inv26);
            g_centers[b][t][3] = (float)((double)spy * invc * (double)ratio);
            g_centers[b][t][4] = (float)((double)spx * invc * (double)ratio);
        }
        // cnt == 0: keep old center (matches jnp.where)
    }
}

// ---------------- fused final-assign + scatter directly into out ------------
// Block = 2 image rows (448 thr, 14 warps; warp = one 32-px row segment so h
// is warp-uniform). Prologue: candidate pruning over the strip, inline argmin
// (same math as k_assign_tile => labels identical). Scatter: match_any
// label-partition; per q, quantize wtq*rgb at 2^26, 3 REDUX over the group
// (all groups concurrent), leader atomically adds wtp*sum into d_out at the
// permuted (s,kc) address. Fixed-point, order-independent => deterministic.
__global__ __launch_bounds__(448) void k_scatter(const float* __restrict__ x,
                                                 float* __restrict__ out) {
    __shared__ float4 scen4[NK];
    __shared__ float2 saux[NK];
    __shared__ unsigned char scand[NK];
    __shared__ unsigned int bal[14];
    __shared__ int sminbits;

    int strip = blockIdx.x, b = blockIdx.y, t = threadIdx.x;
    int lane = t & 31, warp = t >> 5;
    const float ratio = slic_ratio();

    if (t == 0) sminbits = 0x7f7fffff;
    __syncthreads();

    float rmin = 1e30f, rmax = 1e30f;
    float c0 = 0.f, c1 = 0.f, c2 = 0.f, c3 = 0.f, c4 = 0.f;
    if (t < NK) {
        c0 = g_centers[b][t][0];
        c1 = g_centers[b][t][1];
        c2 = g_centers[b][t][2];
        c3 = g_centers[b][t][3];
        c4 = g_centers[b][t][4];
        float ylo = (float)(strip * 2) * ratio, yhi = (float)(strip * 2 + 1) * ratio;
        float xlo = 0.0f, xhi = 223.0f * ratio;
        float dy0 = fmaxf(0.0f, fmaxf(ylo - c3, c3 - yhi));
        float dx0 = fmaxf(0.0f, fmaxf(xlo - c4, c4 - xhi));
        float dy1 = fmaxf(c3 - ylo, yhi - c3);
        float dx1 = fmaxf(c4 - xlo, xhi - c4);
        rmin = dy0 * dy0 + dx0 * dx0;
        rmax = dy1 * dy1 + dx1 * dx1;
    }
    u32 mn = __reduce_min_sync(0xffffffffu, __float_as_uint(rmax));
    if (lane == 0) atomicMin(&sminbits, (int)mn);
    __syncthreads();
    float thresh = __int_as_float(sminbits) + 3.001f;
    bool keep = (t < NK) && (rmin <= thresh);
    unsigned int m = __ballot_sync(0xffffffffu, keep);
    if (lane == 0) bal[warp] = m;
    __syncthreads();
    if (keep) {
        int slot = __popc(m & ((1u << lane) - 1u));
        for (int w2 = 0; w2 < warp; w2++) slot += __popc(bal[w2]);
        scand[slot] = (unsigned char)t;
        scen4[slot] = make_float4(c0, c1, c2, c3);
        saux[slot]  = make_float2(c4, c0*c0 + c1*c1 + c2*c2 + c3*c3 + c4*c4);
    }
    __syncthreads();
    int nc = 0;
#pragma unroll
    for (int w2 = 0; w2 < 14; w2++) nc += __popc(bal[w2]);

    // ---- pixel features + assignment ----
    int row = warp / 7, seg = warp - row * 7;
    int h = strip * 2 + row;
    int w = seg * 32 + lane;
    int i = h * IMGSZ + w;
    const float* im = x + (size_t)b * 3 * HW;
    float r = im[i], g = im[HW + i], bl = im[2 * HW + i];
    float f3 = (float)h * ratio;
    float f4 = (float)w * ratio;
    float fsq = r*r + g*g + bl*bl + f3*f3 + f4*f4;

    float best = 3.4e38f;
    int bs = 0;
    for (int s = 0; s < nc; s++) {
        float4 cc = scen4[s];
        float2 au = saux[s];
        float dot = r * cc.x;
        dot = fmaf(g,  cc.y, dot);
        dot = fmaf(bl, cc.z, dot);
        dot = fmaf(f3, cc.w, dot);
        dot = fmaf(f4, au.x, dot);
        float d = fsq + au.y - 2.0f * dot;
        if (d < best) { best = d; bs = s; }
    }
    int kk = scand[bs];

    // ---- scatter (h warp-uniform) directly into out ----
    int p0 = max(0, (int)ceilf((h - 20.5f) * (1.0f / 14.0f)));
    int p1 = min(NP - 1, (int)floorf((h + 7.5f) * (1.0f / 14.0f)));
    int w0 = seg * 32;
    int qlo = max(0, (int)ceilf((w0 - 20.5f) * (1.0f / 14.0f)));
    int qhi = min(NP - 1, (int)floorf((w0 + 31 + 7.5f) * (1.0f / 14.0f)));

    float* ob = out + (size_t)b * 256 * 300;

    u32 mask = __match_any_sync(0xffffffffu, kk);
    bool leader = (lane == __ffs(mask) - 1);
    for (int q = qlo; q <= qhi; q++) {
        float wtq = g_A[q * IMGSZ + w];              // exactly 0 outside support
        // quantize wtq*rgb at 2^26: |value| <= 0.072*2^26, group sums < 2^31
        u32 q0 = (u32)__float2int_rn(wtq * r  * FIXSCALE);
        u32 q1 = (u32)__float2int_rn(wtq * g  * FIXSCALE);
        u32 q2 = (u32)__float2int_rn(wtq * bl * FIXSCALE);
        u32 s0 = __reduce_add_sync(mask, q0);        // all label-groups concurrent
        u32 s1 = __reduce_add_sync(mask, q1);
        u32 s2 = __reduce_add_sync(mask, q2);
        if (leader) {
            float v0 = (float)s0 * INVFIX;
            float v1 = (float)s1 * INVFIX;
            float v2 = (float)s2 * INVFIX;
            for (int p = p0; p <= p1; p++) {
                float wtp = g_A[p * IMGSZ + h];
                if (wtp != 0.0f) {
                    int lin = ((kk * 16 + p) * 16 + q) * 3;   // channel c adds +c
#pragma unroll
                    for (int c = 0; c < 3; c++) {
                        int lc = lin + c;
                        int s_  = lc & 255;
                        int kc  = lc >> 8;
                        float vv = (c == 0) ? v0 : (c == 1) ? v1 : v2;
                        atomicAdd(ob + s_ * 300 + kc, wtp * vv);
                    }
                }
            }
        }
    }
}

// ---------------- launch ----------------
extern "C" void kernel_launch(void* const* d_in, const int* in_sizes, int n_in,
                              void* d_out, int out_size) {
    const float* x = (const float*)d_in[0];
    float* out = (float*)d_out;

    k_init<<<dim3(NB, 4), 256>>>(x, out);

    dim3 gt(NTT, NB);                    // 98 x 8
    for (int it = 0; it < NITER; it++)
        k_assign_tile<<<gt, 256>>>(x, it);

    k_scatter<<<dim3(112, NB), 448>>>(x, out);   // final assign + scatter into out
}